// round 2
// baseline (speedup 1.0000x reference)
#include <cuda_runtime.h>

// Problem constants (FullChain_58815282152074): N=4096 nodes, d=16, K=16, B=4
#define MB   1024          // nodes per batch (M)
#define NB   4             // num_batches

// Scratch: effective bilinear weight WT[d][e][o] and effective bias
__device__ float g_WT[16 * 16 * 16];
__device__ float g_beff[16];

// ---- packed f32x2 helpers (Blackwell FFMA2) ----
__device__ __forceinline__ unsigned long long ffma2(unsigned long long a,
                                                    unsigned long long b,
                                                    unsigned long long c) {
    unsigned long long d;
    asm("fma.rn.f32x2 %0, %1, %2, %3;" : "=l"(d) : "l"(a), "l"(b), "l"(c));
    return d;
}
__device__ __forceinline__ unsigned long long pack2(float lo, float hi) {
    unsigned long long d;
    asm("mov.b64 %0, {%1, %2};"
        : "=l"(d) : "r"(__float_as_uint(lo)), "r"(__float_as_uint(hi)));
    return d;
}
__device__ __forceinline__ float2 unpack2(unsigned long long v) {
    unsigned int lo, hi;
    asm("mov.b64 {%0, %1}, %2;" : "=r"(lo), "=r"(hi) : "l"(v));
    return make_float2(__uint_as_float(lo), __uint_as_float(hi));
}

// ---------------------------------------------------------------------------
// Kernel A: fold W3@W2 into the bilinear form.
//   C[o,k]     = sum_t W3[o,t] * W2[t,k]
//   WT[d,e,o]  = sum_k C[o,k] * W_bil[k,d,e]     (stored [d][e][o])
//   beff[o]    = sum_k C[o,k]*b_bil[k] + sum_t W3[o,t]*b2[t] + b3[o]
// ---------------------------------------------------------------------------
__global__ void prep_kernel(const float* __restrict__ W_bil,
                            const float* __restrict__ b_bil,
                            const float* __restrict__ W2,
                            const float* __restrict__ b2,
                            const float* __restrict__ W3,
                            const float* __restrict__ b3) {
    __shared__ float Cs[256];
    int tid = threadIdx.x;
    {
        int o = tid >> 4, k = tid & 15;
        float s = 0.f;
#pragma unroll
        for (int t = 0; t < 16; ++t) s += W3[o * 16 + t] * W2[t * 16 + k];
        Cs[tid] = s;
    }
    __syncthreads();
    {
        int d = tid >> 4, e = tid & 15;
#pragma unroll
        for (int o = 0; o < 16; ++o) {
            float s = 0.f;
#pragma unroll
            for (int k = 0; k < 16; ++k)
                s += Cs[o * 16 + k] * W_bil[k * 256 + d * 16 + e];
            g_WT[(d * 16 + e) * 16 + o] = s;
        }
    }
    if (tid < 16) {
        int o = tid;
        float s = b3[o];
#pragma unroll
        for (int k = 0; k < 16; ++k) s += Cs[o * 16 + k] * b_bil[k];
#pragma unroll
        for (int t = 0; t < 16; ++t) s += W3[o * 16 + t] * b2[t];
        g_beff[o] = s;
    }
}

// ---------------------------------------------------------------------------
// Kernel B: one block per (b, i).
//   1. T_i[e,o] = sum_d x_i[d] * WT[d,e,o]   -> shared (256 floats)
//   2. each thread handles 4 j's (2-way unrolled pairs):
//        out[b,i,j,o] = sum_e T_i[e,o]*x_j[e] + beff[o]   via FFMA2
// ---------------------------------------------------------------------------
__global__ __launch_bounds__(256) void edge_kernel(const float* __restrict__ nodes,
                                                   float* __restrict__ out) {
    __shared__ float sx[16];
    __shared__ float sbe[16];
    __shared__ __align__(16) float Ts[256];   // [e][o]

    const int tid = threadIdx.x;
    const int bi  = blockIdx.x;               // b*MB + i
    const int b   = bi >> 10;
    const int i   = bi & (MB - 1);

    if (tid < 16) {
        sx[tid]  = nodes[bi * 16 + tid];
        sbe[tid] = g_beff[tid];
    }
    __syncthreads();
    {
        float t = 0.f;
#pragma unroll
        for (int d = 0; d < 16; ++d) t += sx[d] * g_WT[d * 256 + tid];
        Ts[tid] = t;                          // tid = e*16 + o
    }
    __syncthreads();

    const unsigned long long* Tu = (const unsigned long long*)Ts;  // [e][o/2]

    unsigned long long bias[8];
#pragma unroll
    for (int p = 0; p < 8; ++p) bias[p] = pack2(sbe[2 * p], sbe[2 * p + 1]);

    const float4* Xb = (const float4*)(nodes + (size_t)b * (MB * 16));
    float* outBase = out + (size_t)bi * (MB - 1) * 16;

#pragma unroll
    for (int jj = 0; jj < 2; ++jj) {
        const int j0 = jj * 256 + tid;        // [0,512)
        const int j1 = j0 + 512;              // [512,1024)

        float4 a0 = Xb[j0 * 4 + 0], a1 = Xb[j0 * 4 + 1];
        float4 a2 = Xb[j0 * 4 + 2], a3 = Xb[j0 * 4 + 3];
        float4 c0 = Xb[j1 * 4 + 0], c1 = Xb[j1 * 4 + 1];
        float4 c2 = Xb[j1 * 4 + 2], c3 = Xb[j1 * 4 + 3];

        float x0[16] = {a0.x, a0.y, a0.z, a0.w, a1.x, a1.y, a1.z, a1.w,
                        a2.x, a2.y, a2.z, a2.w, a3.x, a3.y, a3.z, a3.w};
        float x1[16] = {c0.x, c0.y, c0.z, c0.w, c1.x, c1.y, c1.z, c1.w,
                        c2.x, c2.y, c2.z, c2.w, c3.x, c3.y, c3.z, c3.w};

        unsigned long long acc0[8], acc1[8];
#pragma unroll
        for (int p = 0; p < 8; ++p) { acc0[p] = bias[p]; acc1[p] = bias[p]; }

#pragma unroll
        for (int e = 0; e < 16; ++e) {
            unsigned long long xx0 = pack2(x0[e], x0[e]);
            unsigned long long xx1 = pack2(x1[e], x1[e]);
#pragma unroll
            for (int p = 0; p < 8; ++p) {
                unsigned long long tv = Tu[e * 8 + p];  // broadcast LDS.64
                acc0[p] = ffma2(tv, xx0, acc0[p]);
                acc1[p] = ffma2(tv, xx1, acc1[p]);
            }
        }

        if (j0 != i) {
            int r = j0 - (j0 > i);
            float4* po = (float4*)(outBase + (size_t)r * 16);
            float2 v0 = unpack2(acc0[0]), v1 = unpack2(acc0[1]);
            float2 v2 = unpack2(acc0[2]), v3 = unpack2(acc0[3]);
            float2 v4 = unpack2(acc0[4]), v5 = unpack2(acc0[5]);
            float2 v6 = unpack2(acc0[6]), v7 = unpack2(acc0[7]);
            po[0] = make_float4(v0.x, v0.y, v1.x, v1.y);
            po[1] = make_float4(v2.x, v2.y, v3.x, v3.y);
            po[2] = make_float4(v4.x, v4.y, v5.x, v5.y);
            po[3] = make_float4(v6.x, v6.y, v7.x, v7.y);
        }
        if (j1 != i) {
            int r = j1 - (j1 > i);
            float4* po = (float4*)(outBase + (size_t)r * 16);
            float2 v0 = unpack2(acc1[0]), v1 = unpack2(acc1[1]);
            float2 v2 = unpack2(acc1[2]), v3 = unpack2(acc1[3]);
            float2 v4 = unpack2(acc1[4]), v5 = unpack2(acc1[5]);
            float2 v6 = unpack2(acc1[6]), v7 = unpack2(acc1[7]);
            po[0] = make_float4(v0.x, v0.y, v1.x, v1.y);
            po[1] = make_float4(v2.x, v2.y, v3.x, v3.y);
            po[2] = make_float4(v4.x, v4.y, v5.x, v5.y);
            po[3] = make_float4(v6.x, v6.y, v7.x, v7.y);
        }
    }
}

extern "C" void kernel_launch(void* const* d_in, const int* in_sizes, int n_in,
                              void* d_out, int out_size) {
    const float* nodes = (const float*)d_in[0];
    const float* W_bil = (const float*)d_in[1];
    const float* b_bil = (const float*)d_in[2];
    const float* W2    = (const float*)d_in[3];
    const float* b2    = (const float*)d_in[4];
    const float* W3    = (const float*)d_in[5];
    const float* b3    = (const float*)d_in[6];
    float* out = (float*)d_out;

    prep_kernel<<<1, 256>>>(W_bil, b_bil, W2, b2, W3, b3);
    edge_kernel<<<NB * MB, 256>>>(nodes, out);
}